// round 1
// baseline (speedup 1.0000x reference)
#include <cuda_runtime.h>
#include <math.h>

#define BATCH 4
#define SEQ 2048
#define DIM 128
#define QH 16
#define KVH 4
#define WINDOW 512

// Scratch (device globals: allocation-free, allowed by harness rules)
__device__ float g_Q[BATCH * QH * SEQ * DIM];   // [b][h][s][d], pre-scaled by scale*log2e
__device__ float g_K[BATCH * KVH * SEQ * DIM];  // [b][g][s][d]
__device__ float g_V[BATCH * KVH * SEQ * DIM];  // [b][g][s][d]
__device__ float g_A[BATCH * SEQ * QH * DIM];   // [b][s][h*128+d] (attention output, pre-proj)

// ---------------------------------------------------------------------------
// Kernel A: qkv = x @ W_qkv, scatter into g_Q/g_K/g_V.
// M=8192 (b*s), K=128, N=3072. Tile 64x64, 256 threads, 4x4 microtile.
// ---------------------------------------------------------------------------
__global__ void __launch_bounds__(256) qkv_kernel(const float* __restrict__ x,
                                                  const float* __restrict__ Wqkv) {
    __shared__ float Xs[64][66];  // [m][k]
    __shared__ float Ws[64][66];  // [k][n]
    const int m0 = blockIdx.x * 64;
    const int n0 = blockIdx.y * 64;
    const int tid = threadIdx.x;
    const int ty = tid >> 4;     // 0..15 (row group)
    const int tx = tid & 15;     // 0..15 (col group)

    float acc[4][4] = {};

    for (int k0 = 0; k0 < 128; k0 += 64) {
        for (int idx = tid; idx < 64 * 64; idx += 256) {
            int r = idx >> 6, c = idx & 63;
            Xs[r][c] = x[(m0 + r) * 128 + (k0 + c)];
        }
        for (int idx = tid; idx < 64 * 64; idx += 256) {
            int r = idx >> 6, c = idx & 63;
            Ws[r][c] = Wqkv[(k0 + r) * 3072 + (n0 + c)];
        }
        __syncthreads();
#pragma unroll 8
        for (int k = 0; k < 64; k++) {
            float a[4], bb[4];
#pragma unroll
            for (int i = 0; i < 4; i++) a[i] = Xs[ty + 16 * i][k];
#pragma unroll
            for (int j = 0; j < 4; j++) bb[j] = Ws[k][tx + 16 * j];
#pragma unroll
            for (int i = 0; i < 4; i++)
#pragma unroll
                for (int j = 0; j < 4; j++) acc[i][j] += a[i] * bb[j];
        }
        __syncthreads();
    }

    // scale * log2e folded into Q so attention works in exp2 domain
    const float qscale = 1.4426950408889634f * 0.08838834764831845f; // log2e / sqrt(128)

#pragma unroll
    for (int i = 0; i < 4; i++) {
#pragma unroll
        for (int j = 0; j < 4; j++) {
            int m = m0 + ty + 16 * i;
            int n = n0 + tx + 16 * j;
            int b = m >> 11, s = m & 2047;
            int head = n >> 7, d = n & 127;
            float v = acc[i][j];
            if (head < QH) {
                g_Q[((b * QH + head) * SEQ + s) * DIM + d] = v * qscale;
            } else if (head < QH + KVH) {
                g_K[((b * KVH + (head - QH)) * SEQ + s) * DIM + d] = v;
            } else {
                g_V[((b * KVH + (head - QH - KVH)) * SEQ + s) * DIM + d] = v;
            }
        }
    }
}

// ---------------------------------------------------------------------------
// Kernel B: windowed-causal flash attention with ALiBi (exp2 domain).
// Block = (q-tile 64, head, batch); 256 threads.
// S tile: 4x4 per thread (rows ty+16i, cols tx+16j).
// O tile: 4x8 per thread (rows ty+16i, cols tx+16c).
// ---------------------------------------------------------------------------
#define QSTR 130   // padded stride for 128-wide tiles (conflict-free)
#define PSTR 66    // padded stride for 64-wide P tile

__global__ void __launch_bounds__(256) attn_kernel() {
    extern __shared__ float sm[];
    float* Qs = sm;                 // [64][QSTR]
    float* Ks = Qs + 64 * QSTR;     // [64][QSTR]
    float* Vs = Ks + 64 * QSTR;     // [64][QSTR]
    float* Ps = Vs + 64 * QSTR;     // [64][PSTR]

    const int qt = blockIdx.x;      // 0..31
    const int h  = blockIdx.y;      // 0..15
    const int b  = blockIdx.z;      // 0..3
    const int g  = h >> 2;          // kv head
    const float slope2 = exp2f(-(float)(h + 1) * 0.5f) * 1.4426950408889634f;

    const int tid = threadIdx.x;
    const int ty = tid >> 4;
    const int tx = tid & 15;

    const float* Qg = g_Q + ((b * QH + h) * SEQ + qt * 64) * DIM;
    const float* Kg = g_K + (b * KVH + g) * SEQ * DIM;
    const float* Vg = g_V + (b * KVH + g) * SEQ * DIM;

    // load Q tile once
    for (int idx = tid; idx < 64 * 128; idx += 256) {
        int r = idx >> 7, c = idx & 127;
        Qs[r * QSTR + c] = Qg[r * 128 + c];
    }

    float m_i[4], l_i[4], acc[4][8];
#pragma unroll
    for (int i = 0; i < 4; i++) {
        m_i[i] = -1e30f;
        l_i[i] = 0.0f;
#pragma unroll
        for (int c = 0; c < 8; c++) acc[i][c] = 0.0f;
    }

    const int q0 = qt * 64;
    const int kt0 = (q0 >= WINDOW) ? (q0 - WINDOW) : 0;

    for (int kt = kt0; kt <= q0; kt += 64) {
        __syncthreads();  // guards Q (first iter) and Ks/Vs/Ps reuse
        for (int idx = tid; idx < 64 * 128; idx += 256) {
            int r = idx >> 7, c = idx & 127;
            Ks[r * QSTR + c] = Kg[(kt + r) * 128 + c];
            Vs[r * QSTR + c] = Vg[(kt + r) * 128 + c];
        }
        __syncthreads();

        // --- S = Q K^T (already in log2e*scale units) ---
        float s[4][4] = {};
#pragma unroll 8
        for (int k = 0; k < 128; k++) {
            float a[4], kk[4];
#pragma unroll
            for (int i = 0; i < 4; i++) a[i] = Qs[(ty + 16 * i) * QSTR + k];
#pragma unroll
            for (int j = 0; j < 4; j++) kk[j] = Ks[(tx + 16 * j) * QSTR + k];
#pragma unroll
            for (int i = 0; i < 4; i++)
#pragma unroll
                for (int j = 0; j < 4; j++) s[i][j] += a[i] * kk[j];
        }

        // --- ALiBi + window mask ---
#pragma unroll
        for (int i = 0; i < 4; i++) {
#pragma unroll
            for (int j = 0; j < 4; j++) {
                int q = q0 + ty + 16 * i;
                int kc = kt + tx + 16 * j;
                float val = s[i][j] + slope2 * (float)(q - kc);
                bool valid = (kc <= q) && (q - kc <= WINDOW);
                s[i][j] = valid ? val : -1e30f;
            }
        }

        // --- online softmax update (reduce across the 16 tx lanes) ---
#pragma unroll
        for (int i = 0; i < 4; i++) {
            float mt = s[i][0];
#pragma unroll
            for (int j = 1; j < 4; j++) mt = fmaxf(mt, s[i][j]);
#pragma unroll
            for (int off = 8; off >= 1; off >>= 1)
                mt = fmaxf(mt, __shfl_xor_sync(0xffffffffu, mt, off));
            float mnew = fmaxf(m_i[i], mt);
            float alpha = exp2f(m_i[i] - mnew);
            float psum = 0.0f;
#pragma unroll
            for (int j = 0; j < 4; j++) {
                float p = exp2f(s[i][j] - mnew);
                s[i][j] = p;
                psum += p;
            }
#pragma unroll
            for (int off = 8; off >= 1; off >>= 1)
                psum += __shfl_xor_sync(0xffffffffu, psum, off);
            l_i[i] = l_i[i] * alpha + psum;
            m_i[i] = mnew;
#pragma unroll
            for (int c = 0; c < 8; c++) acc[i][c] *= alpha;
        }

        // --- stage P to smem, then O += P @ V ---
#pragma unroll
        for (int i = 0; i < 4; i++)
#pragma unroll
            for (int j = 0; j < 4; j++)
                Ps[(ty + 16 * i) * PSTR + (tx + 16 * j)] = s[i][j];
        __syncthreads();

#pragma unroll 4
        for (int kk2 = 0; kk2 < 64; kk2++) {
            float pr[4], vv[8];
#pragma unroll
            for (int i = 0; i < 4; i++) pr[i] = Ps[(ty + 16 * i) * PSTR + kk2];
#pragma unroll
            for (int c = 0; c < 8; c++) vv[c] = Vs[kk2 * QSTR + (tx + 16 * c)];
#pragma unroll
            for (int i = 0; i < 4; i++)
#pragma unroll
                for (int c = 0; c < 8; c++) acc[i][c] += pr[i] * vv[c];
        }
    }

    // --- normalize and write att to g_A [b][s][h*128+d] ---
#pragma unroll
    for (int i = 0; i < 4; i++) {
        float inv_l = 1.0f / l_i[i];
        int r = ty + 16 * i;
#pragma unroll
        for (int c = 0; c < 8; c++) {
            int col = tx + 16 * c;
            g_A[(((long)b * SEQ + (q0 + r)) * (QH * DIM)) + h * DIM + col] = acc[i][c] * inv_l;
        }
    }
}

// ---------------------------------------------------------------------------
// Kernel C: out = g_A @ W_proj. M=8192, K=2048, N=128.
// Block: 32 rows x 128 cols, 256 threads, 2x8 microtile, K chunks of 64.
// ---------------------------------------------------------------------------
__global__ void __launch_bounds__(256) proj_kernel(const float* __restrict__ Wp,
                                                   float* __restrict__ out) {
    __shared__ float As[32][66];    // [m][k]
    __shared__ float Ws[64][130];   // [k][n]
    const int m0 = blockIdx.x * 32;
    const int tid = threadIdx.x;
    const int ty = tid >> 4;
    const int tx = tid & 15;

    float acc[2][8] = {};

    for (int k0 = 0; k0 < 2048; k0 += 64) {
        for (int idx = tid; idx < 32 * 64; idx += 256) {
            int r = idx >> 6, c = idx & 63;
            As[r][c] = g_A[(long)(m0 + r) * 2048 + (k0 + c)];
        }
        for (int idx = tid; idx < 64 * 128; idx += 256) {
            int r = idx >> 7, c = idx & 127;
            Ws[r][c] = Wp[(k0 + r) * 128 + c];
        }
        __syncthreads();
#pragma unroll 8
        for (int k = 0; k < 64; k++) {
            float a[2], w[8];
#pragma unroll
            for (int i = 0; i < 2; i++) a[i] = As[ty + 16 * i][k];
#pragma unroll
            for (int c = 0; c < 8; c++) w[c] = Ws[k][tx + 16 * c];
#pragma unroll
            for (int i = 0; i < 2; i++)
#pragma unroll
                for (int c = 0; c < 8; c++) acc[i][c] += a[i] * w[c];
        }
        __syncthreads();
    }

#pragma unroll
    for (int i = 0; i < 2; i++)
#pragma unroll
        for (int c = 0; c < 8; c++)
            out[(m0 + ty + 16 * i) * 128 + (tx + 16 * c)] = acc[i][c];
}

// ---------------------------------------------------------------------------
extern "C" void kernel_launch(void* const* d_in, const int* in_sizes, int n_in,
                              void* d_out, int out_size) {
    const float* x     = (const float*)d_in[0];  // (4, 2048, 128)
    const float* Wqkv  = (const float*)d_in[1];  // (128, 3072)
    const float* Wproj = (const float*)d_in[2];  // (2048, 128)
    float* out = (float*)d_out;                  // (4, 2048, 128)

    qkv_kernel<<<dim3(8192 / 64, 3072 / 64), 256>>>(x, Wqkv);

    const int attn_smem = (3 * 64 * QSTR + 64 * PSTR) * (int)sizeof(float); // 116736 B
    cudaFuncSetAttribute(attn_kernel, cudaFuncAttributeMaxDynamicSharedMemorySize, attn_smem);
    attn_kernel<<<dim3(32, 16, 4), 256, attn_smem>>>();

    proj_kernel<<<dim3(8192 / 32), 256>>>(Wproj, out);
}